// round 6
// baseline (speedup 1.0000x reference)
#include <cuda_runtime.h>
#include <cuda_bf16.h>
#include <cstdint>

// Problem: x [32,64,64,64] NCHW fp32, emb0/1/2 [512,64] fp32, idx int
#define NPIX   131072
#define D      64
#define HW     4096
#define KMAX   1024
#define OUT_ELEMS 8388608
#define CTA_PIX 128
#define TPB    128
#define MARGIN_T 0.15f

// smem layout (bytes)
#define SM_A    0            // 128 rows x 256B (xh|xl bf16, swizzled) = 32 KB
#define SM_B0   32768        // 256 rows x 128B (c bf16, swizzled) = 32 KB
#define SM_B1   65536        // second buffer
#define SM_SHN2 98304        // 1024 u32 packed (-norm hi, -norm lo) = 4 KB
#define SMEM_TOTAL 102400
// phase-2 overlays (on B0, dead by then)
#define SM_CS   32768        // 128 x 16 f32 candidate scores
#define SM_CI   40960        // 128 x 16 i32 candidate indices
#define SM_RED2 49152        // 128 f32

// Scratch (no cudaMalloc allowed)
__device__ int      g_hist[KMAX];
__device__ uint32_t g_shn2[KMAX];
__device__ float    g_lossacc;
// bf16 codes, swizzled per-256-row chunk: 4 chunks x 256 rows x 128B
__device__ __align__(16) unsigned char g_bsplit[KMAX * 128];

// ---------------------------------------------------------------------------
__device__ __forceinline__ uint32_t smem_u32(const void* p) {
    uint32_t a;
    asm("{ .reg .u64 t; cvta.to.shared.u64 t, %1; cvt.u32.u64 %0, t; }"
        : "=r"(a) : "l"(p));
    return a;
}

#define LDSM_X4(r0, r1, r2, r3, addr) \
    asm volatile("ldmatrix.sync.aligned.m8n8.x4.shared.b16 {%0,%1,%2,%3}, [%4];" \
        : "=r"(r0), "=r"(r1), "=r"(r2), "=r"(r3) : "r"(addr))

#define MMA(dd, a0, a1, a2, a3, b0, b1) \
    asm volatile("mma.sync.aligned.m16n8k16.row.col.f32.bf16.bf16.f32 " \
        "{%0,%1,%2,%3},{%4,%5,%6,%7},{%8,%9},{%0,%1,%2,%3};" \
        : "+f"((dd)[0]), "+f"((dd)[1]), "+f"((dd)[2]), "+f"((dd)[3]) \
        : "r"(a0), "r"(a1), "r"(a2), "r"(a3), "r"(b0), "r"(b1))

#define CP_ASYNC16(dst, src) \
    asm volatile("cp.async.cg.shared.global [%0], [%1], 16;" :: "r"(dst), "l"(src))
#define CP_COMMIT() asm volatile("cp.async.commit_group;" ::: "memory")
#define CP_WAIT0()  asm volatile("cp.async.wait_group 0;" ::: "memory")

__device__ __forceinline__ const float* code_row(int k, const float* e0,
                                                 const float* e1, const float* e2,
                                                 int idxv) {
    if (k < 512) return e0 + (size_t)k * D;
    const float* e = (idxv == 1) ? e1 : e2;
    return e + (size_t)(k - 512) * D;
}

// ---------------------------------------------------------------------------
// Kernel 0: zero hist/loss + packed bf16-split of (-0.5*||c||^2) per code
// ---------------------------------------------------------------------------
__global__ void prep_norms(const float* __restrict__ e0, const float* __restrict__ e1,
                           const float* __restrict__ e2, const int* __restrict__ idxp) {
    int idxv = *idxp;
    int K = (idxv == 0) ? 512 : 1024;
    int lane = threadIdx.x & 31;
    int k = blockIdx.x * 4 + (threadIdx.x >> 5);
    float s = 0.f;
    if (k < K) {
        const float* c = code_row(k, e0, e1, e2, idxv);
        float a = c[lane], b = c[lane + 32];
        s = a * a + b * b;
    }
    #pragma unroll
    for (int off = 16; off > 0; off >>= 1) s += __shfl_xor_sync(0xffffffffu, s, off);
    if (lane == 0) {
        float neg = -0.5f * s;
        __nv_bfloat16 nh = __float2bfloat16_rn(neg);
        __nv_bfloat16 nl = __float2bfloat16_rn(neg - __bfloat162float(nh));
        g_shn2[k] = (uint32_t)__bfloat16_as_ushort(nh)
                  | ((uint32_t)__bfloat16_as_ushort(nl) << 16);
        g_hist[k] = 0;
        if (k == 0) g_lossacc = 0.f;
    }
}

// ---------------------------------------------------------------------------
// Kernel 1: codes -> bf16, swizzled for ldmatrix (128B rows, 8 16B units).
// swizzle: unit u -> u ^ (row&7)
// ---------------------------------------------------------------------------
__global__ void prep_bsplit(const float* __restrict__ e0, const float* __restrict__ e1,
                            const float* __restrict__ e2, const int* __restrict__ idxp) {
    int idxv = *idxp;
    int K = (idxv == 0) ? 512 : 1024;
    int k = blockIdx.x;
    if (k >= K) return;
    int d = threadIdx.x;                       // 0..63
    float v = code_row(k, e0, e1, e2, idxv)[d];
    __nv_bfloat16 hb = __float2bfloat16_rn(v);
    unsigned char* buf = g_bsplit + (size_t)(k >> 8) * 32768;
    int r = k & 255;
    int u = d >> 3;
    int inb = (2 * d) & 15;
    *(__nv_bfloat16*)(buf + r * 128 + (((u) ^ (r & 7)) << 4) + inb) = hb;
}

// ---------------------------------------------------------------------------
// Kernel 2: HMMA scoring (2-term split: xh.c + xl.c + norm-tile) + top-4
// per-lane tracking + candidate merge + fp64 margin rescue + output/loss/hist.
// ---------------------------------------------------------------------------
__global__ __launch_bounds__(TPB)
void vq_hmma(const float* __restrict__ X,
             const float* __restrict__ e0, const float* __restrict__ e1,
             const float* __restrict__ e2, const int* __restrict__ idxp,
             float* __restrict__ out) {
    extern __shared__ __align__(1024) char smem[];
    const uint32_t sb = smem_u32(smem);
    const int tid = threadIdx.x;
    const int warp = tid >> 5, lane = tid & 31;
    const int q = lane & 3, lr = lane & 7, grp = lane >> 3;
    const int idxv = *idxp;
    const int K = (idxv == 0) ? 512 : 1024;
    const int nch = K >> 8;
    const int pbase = blockIdx.x * CTA_PIX;

    // ---- stage A tile (xh|xl, 256B rows) swizzled + shn2 ----
    {
        int r = tid;
        int p = pbase + r;
        int b = p >> 12;
        size_t xb = (size_t)b * (D * HW) + (p & (HW - 1));
        #pragma unroll
        for (int j = 0; j < 32; j++) {
            float v0 = X[xb + (size_t)(2 * j) * HW];
            float v1 = X[xb + (size_t)(2 * j + 1) * HW];
            __nv_bfloat16 h0 = __float2bfloat16_rn(v0), h1 = __float2bfloat16_rn(v1);
            __nv_bfloat16 l0 = __float2bfloat16_rn(v0 - __bfloat162float(h0));
            __nv_bfloat16 l1 = __float2bfloat16_rn(v1 - __bfloat162float(h1));
            uint32_t hp = (uint32_t)__bfloat16_as_ushort(h0)
                        | ((uint32_t)__bfloat16_as_ushort(h1) << 16);
            uint32_t lp = (uint32_t)__bfloat16_as_ushort(l0)
                        | ((uint32_t)__bfloat16_as_ushort(l1) << 16);
            int u = j >> 2;
            int inb = (4 * j) & 15;
            *(uint32_t*)(smem + SM_A + r * 256 + (((u)     ^ (r & 7)) << 4) + inb) = hp;
            *(uint32_t*)(smem + SM_A + r * 256 + (((u + 8) ^ (r & 7)) << 4) + inb) = lp;
        }
        uint32_t* sh2 = (uint32_t*)(smem + SM_SHN2);
        for (int i = tid; i < KMAX; i += TPB) sh2[i] = g_shn2[i];
    }
    // prefetch B chunk 0 while A finishes
    {
        const char* src = (const char*)g_bsplit + tid * 16;
        uint32_t dst = sb + SM_B0 + tid * 16;
        #pragma unroll
        for (int i = 0; i < 16; i++)
            CP_ASYNC16(dst + i * TPB * 16, src + (size_t)i * TPB * 16);
        CP_COMMIT();
    }
    __syncthreads();

    // ---- persistent A fragments: xh/xl [mtile][ktile][4] ----
    uint32_t xh[2][4][4], xl[2][4][4];
    #pragma unroll
    for (int mt = 0; mt < 2; mt++)
        #pragma unroll
        for (int kt = 0; kt < 4; kt++) {
            int row = warp * 32 + mt * 16 + ((grp & 1) << 3) + lr;
            int uh = kt * 2 + (grp >> 1);
            LDSM_X4(xh[mt][kt][0], xh[mt][kt][1], xh[mt][kt][2], xh[mt][kt][3],
                    sb + SM_A + row * 256 + (((uh) ^ lr) << 4));
            int ul = 8 + kt * 2 + (grp >> 1);
            LDSM_X4(xl[mt][kt][0], xl[mt][kt][1], xl[mt][kt][2], xl[mt][kt][3],
                    sb + SM_A + row * 256 + (((ul) ^ lr) << 4));
        }

    // top-4 per pixel-slot (slot = mt*2 + rowhalf), per-lane 256-code subset
    float ts[4][4];
    int   ti[4][4];
    #pragma unroll
    for (int sl = 0; sl < 4; sl++)
        #pragma unroll
        for (int j = 0; j < 4; j++) { ts[sl][j] = -3.4e38f; ti[sl][j] = 0; }

    const uint32_t aext = (q == 0) ? 0x3F803F80u : 0u;   // (1.0,1.0) bf16
    const uint32_t* sh2 = (const uint32_t*)(smem + SM_SHN2);

    for (int ch = 0; ch < nch; ch++) {
        CP_WAIT0();
        __syncthreads();
        if (ch + 1 < nch) {     // prefetch next chunk into other buffer
            const char* src = (const char*)g_bsplit + (size_t)(ch + 1) * 32768 + tid * 16;
            uint32_t dst = sb + (((ch + 1) & 1) ? SM_B1 : SM_B0) + tid * 16;
            #pragma unroll
            for (int i = 0; i < 16; i++)
                CP_ASYNC16(dst + i * TPB * 16, src + (size_t)i * TPB * 16);
            CP_COMMIT();
        }
        const uint32_t bB = sb + ((ch & 1) ? SM_B1 : SM_B0);
        const int kb = ch << 8;

        #pragma unroll 1
        for (int ng = 0; ng < 16; ng++) {
            const int nt0 = ng * 2;
            float dx[2][2][4];
            #pragma unroll
            for (int a = 0; a < 2; a++)
                #pragma unroll
                for (int bb = 0; bb < 2; bb++)
                    #pragma unroll
                    for (int c = 0; c < 4; c++) dx[a][bb][c] = 0.f;

            // norm k-tile: ones at k0-1 on BOTH row-halves (a0 and a1)
            uint32_t be0 = 0, be1 = 0;
            if (q == 0) {
                be0 = sh2[kb + nt0 * 8 + (lane >> 2)];
                be1 = sh2[kb + nt0 * 8 + 8 + (lane >> 2)];
            }
            MMA(dx[0][0], aext, aext, 0u, 0u, be0, 0u);
            MMA(dx[0][1], aext, aext, 0u, 0u, be1, 0u);
            MMA(dx[1][0], aext, aext, 0u, 0u, be0, 0u);
            MMA(dx[1][1], aext, aext, 0u, 0u, be1, 0u);

            #pragma unroll
            for (int p2 = 0; p2 < 2; p2++) {       // ktile pairs, B shared by xh/xl
                uint32_t b0[4], b1[4];
                {
                    int u = p2 * 4 + grp;
                    int row0 = nt0 * 8 + lr;
                    LDSM_X4(b0[0], b0[1], b0[2], b0[3],
                            bB + row0 * 128 + (((u) ^ lr) << 4));
                    int row1 = (nt0 + 1) * 8 + lr;
                    LDSM_X4(b1[0], b1[1], b1[2], b1[3],
                            bB + row1 * 128 + (((u) ^ lr) << 4));
                }
                #pragma unroll
                for (int k2 = 0; k2 < 2; k2++) {
                    const int kt = p2 * 2 + k2;
                    MMA(dx[0][0], xh[0][kt][0], xh[0][kt][1], xh[0][kt][2], xh[0][kt][3], b0[k2*2], b0[k2*2+1]);
                    MMA(dx[0][1], xh[0][kt][0], xh[0][kt][1], xh[0][kt][2], xh[0][kt][3], b1[k2*2], b1[k2*2+1]);
                    MMA(dx[1][0], xh[1][kt][0], xh[1][kt][1], xh[1][kt][2], xh[1][kt][3], b0[k2*2], b0[k2*2+1]);
                    MMA(dx[1][1], xh[1][kt][0], xh[1][kt][1], xh[1][kt][2], xh[1][kt][3], b1[k2*2], b1[k2*2+1]);
                    MMA(dx[0][0], xl[0][kt][0], xl[0][kt][1], xl[0][kt][2], xl[0][kt][3], b0[k2*2], b0[k2*2+1]);
                    MMA(dx[0][1], xl[0][kt][0], xl[0][kt][1], xl[0][kt][2], xl[0][kt][3], b1[k2*2], b1[k2*2+1]);
                    MMA(dx[1][0], xl[1][kt][0], xl[1][kt][1], xl[1][kt][2], xl[1][kt][3], b0[k2*2], b0[k2*2+1]);
                    MMA(dx[1][1], xl[1][kt][0], xl[1][kt][1], xl[1][kt][2], xl[1][kt][3], b1[k2*2], b1[k2*2+1]);
                }
            }

            // top-4 insert per value
            #pragma unroll
            for (int mt = 0; mt < 2; mt++)
                #pragma unroll
                for (int j = 0; j < 2; j++) {
                    const int nb = kb + (nt0 + j) * 8 + q * 2;
                    #pragma unroll
                    for (int e = 0; e < 4; e++) {
                        const int sl = mt * 2 + (e >> 1);
                        const int kk = nb + (e & 1);
                        float v = dx[mt][j][e];
                        if (v > ts[sl][3]) {
                            if (v > ts[sl][1]) {
                                ts[sl][3] = ts[sl][2]; ti[sl][3] = ti[sl][2];
                                ts[sl][2] = ts[sl][1]; ti[sl][2] = ti[sl][1];
                                if (v > ts[sl][0]) {
                                    ts[sl][1] = ts[sl][0]; ti[sl][1] = ti[sl][0];
                                    ts[sl][0] = v; ti[sl][0] = kk;
                                } else { ts[sl][1] = v; ti[sl][1] = kk; }
                            } else {
                                if (v > ts[sl][2]) {
                                    ts[sl][3] = ts[sl][2]; ti[sl][3] = ti[sl][2];
                                    ts[sl][2] = v; ti[sl][2] = kk;
                                } else { ts[sl][3] = v; ti[sl][3] = kk; }
                            }
                        }
                    }
                }
        }
        __syncthreads();   // all reads of this B buffer done before its reuse
    }

    // ---- publish candidates (overlay on dead B0) ----
    {
        float* CS = (float*)(smem + SM_CS);
        int*   CI = (int*)(smem + SM_CI);
        #pragma unroll
        for (int sl = 0; sl < 4; sl++) {
            int pl = warp * 32 + (sl >> 1) * 16 + (sl & 1) * 8 + (lane >> 2);
            #pragma unroll
            for (int j = 0; j < 4; j++) {
                CS[pl * 16 + q * 4 + j] = ts[sl][j];
                CI[pl * 16 + q * 4 + j] = ti[sl][j];
            }
        }
    }
    __syncthreads();

    // ---- phase 2: merge 16 candidates, margin rescue, output/loss/hist ----
    {
        const int p = pbase + tid;
        const int b = p >> 12;
        const size_t xb = (size_t)b * (D * HW) + (p & (HW - 1));
        float cs[16]; int ci[16];
        {
            const float* CS = (const float*)(smem + SM_CS);
            const int*   CI = (const int*)(smem + SM_CI);
            #pragma unroll
            for (int m = 0; m < 16; m++) { cs[m] = CS[tid * 16 + m]; ci[m] = CI[tid * 16 + m]; }
        }
        float s1 = -3.4e38f, s2 = -3.4e38f; int w1 = 0;
        #pragma unroll
        for (int m = 0; m < 16; m++) {
            if (cs[m] > s1) { s2 = s1; s1 = cs[m]; w1 = ci[m]; }
            else if (cs[m] > s2) s2 = cs[m];
        }

        float xr[D];
        #pragma unroll 8
        for (int d = 0; d < D; d++) xr[d] = X[xb + (size_t)d * HW];

        if (s1 - s2 < MARGIN_T) {     // exact re-rank of in-window candidates
            double bd = 1e300; int bi = 0x7fffffff;
            for (int m = 0; m < 16; m++) {
                if (cs[m] > s1 - MARGIN_T) {
                    const float* c = code_row(ci[m], e0, e1, e2, idxv);
                    double dd = 0.0;
                    for (int d = 0; d < D; d++) {
                        double t = (double)xr[d] - (double)c[d];
                        dd += t * t;
                    }
                    if (dd < bd || (dd == bd && ci[m] < bi)) { bd = dd; bi = ci[m]; }
                }
            }
            w1 = bi;
        }
        atomicAdd(&g_hist[w1], 1);

        const float* cw = code_row(w1, e0, e1, e2, idxv);
        float lsum = 0.f;
        #pragma unroll 8
        for (int d = 0; d < D; d++) {
            float df = cw[d] - xr[d];
            out[xb + (size_t)d * HW] = xr[d] + df;   // STE, reference rounding
            lsum += df * df;
        }
        float* red = (float*)(smem + SM_RED2);
        red[tid] = lsum;
        __syncthreads();
        for (int off = TPB / 2; off > 0; off >>= 1) {
            if (tid < off) red[tid] += red[tid + off];
            __syncthreads();
        }
        if (tid == 0) atomicAdd(&g_lossacc, red[0]);
    }
}

// ---------------------------------------------------------------------------
// Kernel 3: finalize loss + perplexity
// ---------------------------------------------------------------------------
__global__ void finalize_kernel(const int* __restrict__ idxp, float* __restrict__ out,
                                int out_size) {
    __shared__ float red[1024];
    int t = threadIdx.x;
    int idxv = *idxp;
    int K = (idxv == 0) ? 512 : 1024;
    float v = 0.f;
    if (t < K) {
        float pr = (float)g_hist[t] * (1.0f / (float)NPIX);
        v = pr * logf(pr + 1e-10f);
    }
    red[t] = v;
    __syncthreads();
    for (int off = 512; off > 0; off >>= 1) {
        if (t < off) red[t] += red[t + off];
        __syncthreads();
    }
    if (t == 0) {
        float mse = g_lossacc / (float)OUT_ELEMS;
        out[OUT_ELEMS]     = mse + 0.25f * mse;   // q_latent + 0.25*e_latent
        out[OUT_ELEMS + 1] = expf(-red[0]);       // perplexity
    }
    for (int i = OUT_ELEMS + 2 + t; i < out_size; i += 1024) out[i] = 0.f;
}

// ---------------------------------------------------------------------------
extern "C" void kernel_launch(void* const* d_in, const int* in_sizes, int n_in,
                              void* d_out, int out_size) {
    const float* x  = (const float*)d_in[0];
    const float* e0 = (const float*)d_in[1];
    const float* e1 = (const float*)d_in[2];
    const float* e2 = (const float*)d_in[3];
    const int*   ip = (const int*)d_in[4];
    float* out = (float*)d_out;

    cudaFuncSetAttribute(vq_hmma, cudaFuncAttributeMaxDynamicSharedMemorySize,
                         SMEM_TOTAL);

    prep_norms<<<256, 128>>>(e0, e1, e2, ip);
    prep_bsplit<<<KMAX, 64>>>(e0, e1, e2, ip);
    vq_hmma<<<NPIX / CTA_PIX, TPB, SMEM_TOTAL>>>(x, e0, e1, e2, ip, out);
    finalize_kernel<<<1, 1024>>>(ip, out, out_size);
}

// round 9
// speedup vs baseline: 1.0104x; 1.0104x over previous
#include <cuda_runtime.h>
#include <cuda_bf16.h>
#include <cstdint>

// Problem: x [32,64,64,64] NCHW fp32, emb0/1/2 [512,64] fp32, idx int
#define NPIX   131072
#define D      64
#define HW     4096
#define KMAX   1024
#define OUT_ELEMS 8388608
#define CTA_PIX 256
#define TPB    256
#define MARGIN_T 0.25f

// smem layout (bytes)
#define SM_A    0            // 256 rows x 256B (xh|xl bf16, swizzled) = 64 KB
#define SM_B0   65536        // 256 rows x 128B (c bf16, swizzled) = 32 KB
#define SM_B1   98304        // second buffer = 32 KB
#define SM_SHN  131072       // 1024 f32 (-0.5||c||^2) = 4 KB
#define SMEM_TOTAL 135168
// phase-2 overlays (on B0, dead after last epilogue)
#define SM_KEY  65536        // 256 x 12 u32 candidate keys (12 KB)
#define SM_RED2 81920        // 256 f32

// Scratch (no cudaMalloc allowed)
__device__ int      g_hist[KMAX];
__device__ float    g_shn[KMAX];
__device__ float    g_lossacc;
// bf16 codes, swizzled per-256-row chunk: 4 chunks x 256 rows x 128B
__device__ __align__(16) unsigned char g_bsplit[KMAX * 128];

// ---------------------------------------------------------------------------
__device__ __forceinline__ uint32_t smem_u32(const void* p) {
    uint32_t a;
    asm("{ .reg .u64 t; cvta.to.shared.u64 t, %1; cvt.u32.u64 %0, t; }"
        : "=r"(a) : "l"(p));
    return a;
}

#define LDSM_X4(r0, r1, r2, r3, addr) \
    asm volatile("ldmatrix.sync.aligned.m8n8.x4.shared.b16 {%0,%1,%2,%3}, [%4];" \
        : "=r"(r0), "=r"(r1), "=r"(r2), "=r"(r3) : "r"(addr))

#define MMA(dd, a0, a1, a2, a3, b0, b1) \
    asm volatile("mma.sync.aligned.m16n8k16.row.col.f32.bf16.bf16.f32 " \
        "{%0,%1,%2,%3},{%4,%5,%6,%7},{%8,%9},{%0,%1,%2,%3};" \
        : "+f"((dd)[0]), "+f"((dd)[1]), "+f"((dd)[2]), "+f"((dd)[3]) \
        : "r"(a0), "r"(a1), "r"(a2), "r"(a3), "r"(b0), "r"(b1))

#define CP_ASYNC16(dst, src) \
    asm volatile("cp.async.cg.shared.global [%0], [%1], 16;" :: "r"(dst), "l"(src))
#define CP_COMMIT() asm volatile("cp.async.commit_group;" ::: "memory")
#define CP_WAIT0()  asm volatile("cp.async.wait_group 0;" ::: "memory")

__device__ __forceinline__ const float* code_row(int k, const float* e0,
                                                 const float* e1, const float* e2,
                                                 int idxv) {
    if (k < 512) return e0 + (size_t)k * D;
    const float* e = (idxv == 1) ? e1 : e2;
    return e + (size_t)(k - 512) * D;
}

// Order-preserving fp32 -> u32 (monotone for unsigned compare)
__device__ __forceinline__ uint32_t enc_f32(float f) {
    int s = __float_as_int(f);
    return (uint32_t)(s ^ ((s >> 31) | 0x80000000));
}
__device__ __forceinline__ float dec_u32(uint32_t u) {
    uint32_t v = (u & 0x80000000u) ? (u ^ 0x80000000u) : ~u;
    return __int_as_float((int)v);
}

// ---------------------------------------------------------------------------
// Kernel 0: zero hist/loss + fp32 (-0.5*||c||^2) per code (one warp per code)
// ---------------------------------------------------------------------------
__global__ void prep_norms(const float* __restrict__ e0, const float* __restrict__ e1,
                           const float* __restrict__ e2, const int* __restrict__ idxp) {
    int idxv = *idxp;
    int K = (idxv == 0) ? 512 : 1024;
    int lane = threadIdx.x & 31;
    int k = blockIdx.x * 4 + (threadIdx.x >> 5);
    float s = 0.f;
    if (k < K) {
        const float* c = code_row(k, e0, e1, e2, idxv);
        float a = c[lane], b = c[lane + 32];
        s = a * a + b * b;
    }
    #pragma unroll
    for (int off = 16; off > 0; off >>= 1) s += __shfl_xor_sync(0xffffffffu, s, off);
    if (lane == 0) {
        g_shn[k] = -0.5f * s;
        g_hist[k] = 0;
        if (k == 0) g_lossacc = 0.f;
    }
}

// ---------------------------------------------------------------------------
// Kernel 1: codes -> bf16, swizzled for ldmatrix (128B rows, 8 16B units).
// swizzle: unit u -> u ^ (row&7)
// ---------------------------------------------------------------------------
__global__ void prep_bsplit(const float* __restrict__ e0, const float* __restrict__ e1,
                            const float* __restrict__ e2, const int* __restrict__ idxp) {
    int idxv = *idxp;
    int K = (idxv == 0) ? 512 : 1024;
    int k = blockIdx.x;
    if (k >= K) return;
    int d = threadIdx.x;                       // 0..63
    float v = code_row(k, e0, e1, e2, idxv)[d];
    __nv_bfloat16 hb = __float2bfloat16_rn(v);
    unsigned char* buf = g_bsplit + (size_t)(k >> 8) * 32768;
    int r = k & 255;
    int u = d >> 3;
    int inb = (2 * d) & 15;
    *(__nv_bfloat16*)(buf + r * 128 + (((u) ^ (r & 7)) << 4) + inb) = hb;
}

// ---------------------------------------------------------------------------
// Kernel 2: HMMA scoring (2-term split: xh.c + xl.c; norms added in epilogue)
// + branch-free top-3-per-lane (sortable-u32 keys, IMNMX chain)
// + candidate merge + fp64 margin rescue + output/loss/hist.
// ---------------------------------------------------------------------------
__global__ __launch_bounds__(TPB)
void vq_hmma(const float* __restrict__ X,
             const float* __restrict__ e0, const float* __restrict__ e1,
             const float* __restrict__ e2, const int* __restrict__ idxp,
             float* __restrict__ out) {
    extern __shared__ __align__(1024) char smem[];
    const uint32_t sb = smem_u32(smem);
    const int tid = threadIdx.x;
    const int warp = tid >> 5, lane = tid & 31;
    const int q = lane & 3, lr = lane & 7, grp = lane >> 3;
    const int idxv = *idxp;
    const int K = (idxv == 0) ? 512 : 1024;
    const int nch = K >> 8;
    const int pbase = blockIdx.x * CTA_PIX;

    // ---- stage A tile (xh|xl, 256B rows) swizzled + norms ----
    {
        int r = tid;
        int p = pbase + r;
        int b = p >> 12;
        size_t xb = (size_t)b * (D * HW) + (p & (HW - 1));
        #pragma unroll
        for (int j = 0; j < 32; j++) {
            float v0 = X[xb + (size_t)(2 * j) * HW];
            float v1 = X[xb + (size_t)(2 * j + 1) * HW];
            __nv_bfloat16 h0 = __float2bfloat16_rn(v0), h1 = __float2bfloat16_rn(v1);
            __nv_bfloat16 l0 = __float2bfloat16_rn(v0 - __bfloat162float(h0));
            __nv_bfloat16 l1 = __float2bfloat16_rn(v1 - __bfloat162float(h1));
            uint32_t hp = (uint32_t)__bfloat16_as_ushort(h0)
                        | ((uint32_t)__bfloat16_as_ushort(h1) << 16);
            uint32_t lp = (uint32_t)__bfloat16_as_ushort(l0)
                        | ((uint32_t)__bfloat16_as_ushort(l1) << 16);
            int u = j >> 2;
            int inb = (4 * j) & 15;
            *(uint32_t*)(smem + SM_A + r * 256 + (((u)     ^ (r & 7)) << 4) + inb) = hp;
            *(uint32_t*)(smem + SM_A + r * 256 + (((u + 8) ^ (r & 7)) << 4) + inb) = lp;
        }
        float* shn = (float*)(smem + SM_SHN);
        for (int i = tid; i < KMAX; i += TPB) shn[i] = g_shn[i];
    }
    // prefetch B chunk 0
    {
        const char* src = (const char*)g_bsplit + tid * 16;
        uint32_t dst = sb + SM_B0 + tid * 16;
        #pragma unroll
        for (int i = 0; i < 8; i++)
            CP_ASYNC16(dst + i * TPB * 16, src + (size_t)i * TPB * 16);
        CP_COMMIT();
    }
    __syncthreads();

    // ---- persistent A fragments: xh/xl [mtile][ktile][4] ----
    uint32_t xh[2][4][4], xl[2][4][4];
    #pragma unroll
    for (int mt = 0; mt < 2; mt++)
        #pragma unroll
        for (int kt = 0; kt < 4; kt++) {
            int row = warp * 32 + mt * 16 + ((grp & 1) << 3) + lr;
            int uh = kt * 2 + (grp >> 1);
            LDSM_X4(xh[mt][kt][0], xh[mt][kt][1], xh[mt][kt][2], xh[mt][kt][3],
                    sb + SM_A + row * 256 + (((uh) ^ lr) << 4));
            int ul = 8 + kt * 2 + (grp >> 1);
            LDSM_X4(xl[mt][kt][0], xl[mt][kt][1], xl[mt][kt][2], xl[mt][kt][3],
                    sb + SM_A + row * 256 + (((ul) ^ lr) << 4));
        }

    // top-3 keys per pixel-slot (slot = mt*2 + rowhalf), branch-free
    uint32_t tkey[4][3];
    #pragma unroll
    for (int sl = 0; sl < 4; sl++) { tkey[sl][0] = 0; tkey[sl][1] = 0; tkey[sl][2] = 0; }

    const float2* shnf = (const float2*)(smem + SM_SHN);

    for (int ch = 0; ch < nch; ch++) {
        CP_WAIT0();
        __syncthreads();
        if (ch + 1 < nch) {
            const char* src = (const char*)g_bsplit + (size_t)(ch + 1) * 32768 + tid * 16;
            uint32_t dst = sb + (((ch + 1) & 1) ? SM_B1 : SM_B0) + tid * 16;
            #pragma unroll
            for (int i = 0; i < 8; i++)
                CP_ASYNC16(dst + i * TPB * 16, src + (size_t)i * TPB * 16);
            CP_COMMIT();
        }
        const uint32_t bB = sb + ((ch & 1) ? SM_B1 : SM_B0);
        const int kb = ch << 8;

        #pragma unroll 1
        for (int ng = 0; ng < 16; ng++) {
            const int nt0 = ng * 2;
            float dx[2][2][4];
            #pragma unroll
            for (int a = 0; a < 2; a++)
                #pragma unroll
                for (int bb = 0; bb < 2; bb++)
                    #pragma unroll
                    for (int c = 0; c < 4; c++) dx[a][bb][c] = 0.f;

            #pragma unroll
            for (int p2 = 0; p2 < 2; p2++) {       // ktile pairs, B shared by xh/xl
                uint32_t b0[4], b1[4];
                {
                    int u = p2 * 4 + grp;
                    int row0 = nt0 * 8 + lr;
                    LDSM_X4(b0[0], b0[1], b0[2], b0[3],
                            bB + row0 * 128 + (((u) ^ lr) << 4));
                    int row1 = (nt0 + 1) * 8 + lr;
                    LDSM_X4(b1[0], b1[1], b1[2], b1[3],
                            bB + row1 * 128 + (((u) ^ lr) << 4));
                }
                #pragma unroll
                for (int k2 = 0; k2 < 2; k2++) {
                    const int kt = p2 * 2 + k2;
                    MMA(dx[0][0], xh[0][kt][0], xh[0][kt][1], xh[0][kt][2], xh[0][kt][3], b0[k2*2], b0[k2*2+1]);
                    MMA(dx[0][1], xh[0][kt][0], xh[0][kt][1], xh[0][kt][2], xh[0][kt][3], b1[k2*2], b1[k2*2+1]);
                    MMA(dx[1][0], xh[1][kt][0], xh[1][kt][1], xh[1][kt][2], xh[1][kt][3], b0[k2*2], b0[k2*2+1]);
                    MMA(dx[1][1], xh[1][kt][0], xh[1][kt][1], xh[1][kt][2], xh[1][kt][3], b1[k2*2], b1[k2*2+1]);
                    MMA(dx[0][0], xl[0][kt][0], xl[0][kt][1], xl[0][kt][2], xl[0][kt][3], b0[k2*2], b0[k2*2+1]);
                    MMA(dx[0][1], xl[0][kt][0], xl[0][kt][1], xl[0][kt][2], xl[0][kt][3], b1[k2*2], b1[k2*2+1]);
                    MMA(dx[1][0], xl[1][kt][0], xl[1][kt][1], xl[1][kt][2], xl[1][kt][3], b0[k2*2], b0[k2*2+1]);
                    MMA(dx[1][1], xl[1][kt][0], xl[1][kt][1], xl[1][kt][2], xl[1][kt][3], b1[k2*2], b1[k2*2+1]);
                }
            }

            // branch-free epilogue: +norm, encode, 5-op IMNMX top-3 insert.
            // Norm index MUST include the chunk base kb (R8 bug: omitted).
            float2 nA = shnf[(kb + nt0 * 8 + q * 2) >> 1];
            float2 nB = shnf[(kb + (nt0 + 1) * 8 + q * 2) >> 1];
            #pragma unroll
            for (int mt = 0; mt < 2; mt++)
                #pragma unroll
                for (int j = 0; j < 2; j++) {
                    const int nb = kb + (nt0 + j) * 8 + q * 2;
                    const float2 nn = j ? nB : nA;
                    #pragma unroll
                    for (int e = 0; e < 4; e++) {
                        const int sl = mt * 2 + (e >> 1);
                        float v = dx[mt][j][e] + ((e & 1) ? nn.y : nn.x);
                        uint32_t key = (enc_f32(v) & 0xFFFFFC00u)
                                     | (uint32_t)(nb + (e & 1));
                        uint32_t a = max(key, tkey[sl][0]);
                        uint32_t b = min(key, tkey[sl][0]);
                        tkey[sl][0] = a;
                        uint32_t c = max(b, tkey[sl][1]);
                        uint32_t d = min(b, tkey[sl][1]);
                        tkey[sl][1] = c;
                        tkey[sl][2] = max(d, tkey[sl][2]);
                    }
                }
        }
        __syncthreads();   // all reads of this B buffer done before reuse
    }

    // ---- publish candidates (overlay on dead B0) ----
    {
        uint32_t* KEY = (uint32_t*)(smem + SM_KEY);
        #pragma unroll
        for (int sl = 0; sl < 4; sl++) {
            int pl = warp * 32 + (sl >> 1) * 16 + (sl & 1) * 8 + (lane >> 2);
            #pragma unroll
            for (int j = 0; j < 3; j++)
                KEY[pl * 12 + q * 3 + j] = tkey[sl][j];
        }
    }
    __syncthreads();

    // ---- phase 2: merge 12 candidates, margin rescue, output/loss/hist ----
    {
        const int p = pbase + tid;
        const int b = p >> 12;
        const size_t xb = (size_t)b * (D * HW) + (p & (HW - 1));
        uint32_t ck[12];
        {
            const uint32_t* KEY = (const uint32_t*)(smem + SM_KEY);
            #pragma unroll
            for (int m = 0; m < 12; m++) ck[m] = KEY[tid * 12 + m];
        }
        uint32_t k1 = 0, k2 = 0;
        #pragma unroll
        for (int m = 0; m < 12; m++) {
            uint32_t a = max(ck[m], k1);
            uint32_t bb = min(ck[m], k1);
            k1 = a;
            k2 = max(bb, k2);
        }
        int w1 = (int)(k1 & 1023u);
        float s1 = dec_u32(k1), s2 = dec_u32(k2);

        float xr[D];
        #pragma unroll 8
        for (int d = 0; d < D; d++) xr[d] = X[xb + (size_t)d * HW];

        if (s1 - s2 < MARGIN_T) {     // exact fp64 re-rank of in-window cands
            double bd = 1e300; int bi = 0x7fffffff;
            float thr = s1 - MARGIN_T;
            for (int m = 0; m < 12; m++) {
                if (dec_u32(ck[m]) > thr) {
                    int cidx = (int)(ck[m] & 1023u);
                    const float* c = code_row(cidx, e0, e1, e2, idxv);
                    double dd = 0.0;
                    for (int d = 0; d < D; d++) {
                        double t = (double)xr[d] - (double)c[d];
                        dd += t * t;
                    }
                    if (dd < bd || (dd == bd && cidx < bi)) { bd = dd; bi = cidx; }
                }
            }
            w1 = bi;
        }
        atomicAdd(&g_hist[w1], 1);

        const float* cw = code_row(w1, e0, e1, e2, idxv);
        float lsum = 0.f;
        #pragma unroll 8
        for (int d = 0; d < D; d++) {
            float df = cw[d] - xr[d];
            out[xb + (size_t)d * HW] = xr[d] + df;   // STE, reference rounding
            lsum += df * df;
        }
        float* red = (float*)(smem + SM_RED2);
        red[tid] = lsum;
        __syncthreads();
        for (int off = TPB / 2; off > 0; off >>= 1) {
            if (tid < off) red[tid] += red[tid + off];
            __syncthreads();
        }
        if (tid == 0) atomicAdd(&g_lossacc, red[0]);
    }
}

// ---------------------------------------------------------------------------
// Kernel 3: finalize loss + perplexity
// ---------------------------------------------------------------------------
__global__ void finalize_kernel(const int* __restrict__ idxp, float* __restrict__ out,
                                int out_size) {
    __shared__ float red[1024];
    int t = threadIdx.x;
    int idxv = *idxp;
    int K = (idxv == 0) ? 512 : 1024;
    float v = 0.f;
    if (t < K) {
        float pr = (float)g_hist[t] * (1.0f / (float)NPIX);
        v = pr * logf(pr + 1e-10f);
    }
    red[t] = v;
    __syncthreads();
    for (int off = 512; off > 0; off >>= 1) {
        if (t < off) red[t] += red[t + off];
        __syncthreads();
    }
    if (t == 0) {
        float mse = g_lossacc / (float)OUT_ELEMS;
        out[OUT_ELEMS]     = mse + 0.25f * mse;   // q_latent + 0.25*e_latent
        out[OUT_ELEMS + 1] = expf(-red[0]);       // perplexity
    }
    for (int i = OUT_ELEMS + 2 + t; i < out_size; i += 1024) out[i] = 0.f;
}

// ---------------------------------------------------------------------------
extern "C" void kernel_launch(void* const* d_in, const int* in_sizes, int n_in,
                              void* d_out, int out_size) {
    const float* x  = (const float*)d_in[0];
    const float* e0 = (const float*)d_in[1];
    const float* e1 = (const float*)d_in[2];
    const float* e2 = (const float*)d_in[3];
    const int*   ip = (const int*)d_in[4];
    float* out = (float*)d_out;

    cudaFuncSetAttribute(vq_hmma, cudaFuncAttributeMaxDynamicSharedMemorySize,
                         SMEM_TOTAL);

    prep_norms<<<256, 128>>>(e0, e1, e2, ip);
    prep_bsplit<<<KMAX, 64>>>(e0, e1, e2, ip);
    vq_hmma<<<NPIX / CTA_PIX, TPB, SMEM_TOTAL>>>(x, e0, e1, e2, ip, out);
    finalize_kernel<<<1, 1024>>>(ip, out, out_size);
}

// round 10
// speedup vs baseline: 2.2796x; 2.2561x over previous
#include <cuda_runtime.h>
#include <cuda_bf16.h>
#include <cstdint>

// Problem: x [32,64,64,64] NCHW fp32, emb0/1/2 [512,64] fp32, idx int
#define NPIX   131072
#define D      64
#define HW     4096
#define KMAX   1024
#define OUT_ELEMS 8388608
#define CTA_PIX 256
#define TPB    256

// smem layout (bytes). B OVERLAYS A: A (64 KB staging) is dead once the
// persistent register fragments are loaded, so the per-chunk B buffer reuses
// the same region. Total 70 KB -> 2 CTAs/SM (vs R5's 135 KB -> 1 CTA/SM).
#define SM_A    0            // 256 rows x 256B (xh|xl bf16, swizzled) = 64 KB
#define SM_B    0            // 256 rows x 256B (ch|cl bf16, swizzled) overlay
#define SM_SHN2 65536        // 1024 u32 packed (-norm hi, -norm lo) = 4 KB
#define SMEM_TOTAL 70656
// phase-2 overlays (inside dead B region, after final chunk's syncthreads)
#define SM_S1   0            // 256 f32
#define SM_S2   1024
#define SM_I1   2048         // 256 i32
#define SM_I2   3072
#define SM_RED  4096         // 256 f32

// Scratch (no cudaMalloc allowed)
__device__ int      g_hist[KMAX];
__device__ uint32_t g_shn2[KMAX];
__device__ float    g_lossacc;
// Pre-split codes, swizzled chunk layout: 4 chunks x 256 rows x 256B
__device__ __align__(16) unsigned char g_bsplit[KMAX * 256];

// ---------------------------------------------------------------------------
__device__ __forceinline__ uint32_t smem_u32(const void* p) {
    uint32_t a;
    asm("{ .reg .u64 t; cvta.to.shared.u64 t, %1; cvt.u32.u64 %0, t; }"
        : "=r"(a) : "l"(p));
    return a;
}

#define LDSM_X4(r0, r1, r2, r3, addr) \
    asm volatile("ldmatrix.sync.aligned.m8n8.x4.shared.b16 {%0,%1,%2,%3}, [%4];" \
        : "=r"(r0), "=r"(r1), "=r"(r2), "=r"(r3) : "r"(addr))

#define MMA(dd, a0, a1, a2, a3, b0, b1) \
    asm volatile("mma.sync.aligned.m16n8k16.row.col.f32.bf16.bf16.f32 " \
        "{%0,%1,%2,%3},{%4,%5,%6,%7},{%8,%9},{%0,%1,%2,%3};" \
        : "+f"((dd)[0]), "+f"((dd)[1]), "+f"((dd)[2]), "+f"((dd)[3]) \
        : "r"(a0), "r"(a1), "r"(a2), "r"(a3), "r"(b0), "r"(b1))

__device__ __forceinline__ const float* code_row(int k, const float* e0,
                                                 const float* e1, const float* e2,
                                                 int idxv) {
    if (k < 512) return e0 + (size_t)k * D;
    const float* e = (idxv == 1) ? e1 : e2;
    return e + (size_t)(k - 512) * D;
}

// ---------------------------------------------------------------------------
// Kernel 0: zero hist/loss + packed bf16-split of (-0.5*||c||^2) per code
// ---------------------------------------------------------------------------
__global__ void prep_norms(const float* __restrict__ e0, const float* __restrict__ e1,
                           const float* __restrict__ e2, const int* __restrict__ idxp) {
    int idxv = *idxp;
    int K = (idxv == 0) ? 512 : 1024;
    int lane = threadIdx.x & 31;
    int k = blockIdx.x * 4 + (threadIdx.x >> 5);
    float s = 0.f;
    if (k < K) {
        const float* c = code_row(k, e0, e1, e2, idxv);
        float a = c[lane], b = c[lane + 32];
        s = a * a + b * b;
    }
    #pragma unroll
    for (int off = 16; off > 0; off >>= 1) s += __shfl_xor_sync(0xffffffffu, s, off);
    if (lane == 0) {
        float neg = -0.5f * s;
        __nv_bfloat16 nh = __float2bfloat16_rn(neg);
        __nv_bfloat16 nl = __float2bfloat16_rn(neg - __bfloat162float(nh));
        g_shn2[k] = (uint32_t)__bfloat16_as_ushort(nh)
                  | ((uint32_t)__bfloat16_as_ushort(nl) << 16);
        g_hist[k] = 0;
        if (k == 0) g_lossacc = 0.f;
    }
}

// ---------------------------------------------------------------------------
// Kernel 1: bf16-split codes -> g_bsplit, swizzled for ldmatrix.
// row = code%256 within chunk; ch at byte cols 0..127, cl at 128..255.
// swizzle: 16B-unit u -> u ^ (row&7)
// ---------------------------------------------------------------------------
__global__ void prep_bsplit(const float* __restrict__ e0, const float* __restrict__ e1,
                            const float* __restrict__ e2, const int* __restrict__ idxp) {
    int idxv = *idxp;
    int K = (idxv == 0) ? 512 : 1024;
    int k = blockIdx.x;
    if (k >= K) return;
    int d = threadIdx.x;                       // 0..63
    float v = code_row(k, e0, e1, e2, idxv)[d];
    __nv_bfloat16 hb = __float2bfloat16_rn(v);
    __nv_bfloat16 lb = __float2bfloat16_rn(v - __bfloat162float(hb));
    unsigned char* buf = g_bsplit + (size_t)(k >> 8) * 65536;
    int r = k & 255;
    int u = d >> 3;                            // (2d)/16
    int inb = (2 * d) & 15;
    *(__nv_bfloat16*)(buf + r * 256 + (((u)     ^ (r & 7)) << 4) + inb) = hb;
    *(__nv_bfloat16*)(buf + r * 256 + (((u + 8) ^ (r & 7)) << 4) + inb) = lb;
}

// ---------------------------------------------------------------------------
// Kernel 2: HMMA scoring + top-2 argmax + rescue + output/loss/hist.
// score = x.c - 0.5||c||^2 via bf16 split (xh.ch + xh.cl + xl.ch) plus a
// norm k-tile (A col of ones x B col of split -norm). argmax == argmin dist.
// ---------------------------------------------------------------------------
__global__ __launch_bounds__(TPB, 2)
void vq_hmma(const float* __restrict__ X,
             const float* __restrict__ e0, const float* __restrict__ e1,
             const float* __restrict__ e2, const int* __restrict__ idxp,
             float* __restrict__ out) {
    extern __shared__ __align__(1024) char smem[];
    const uint32_t sb = smem_u32(smem);
    const int tid = threadIdx.x;
    const int warp = tid >> 5, lane = tid & 31;
    const int q = lane & 3, lr = lane & 7, grp = lane >> 3;
    const int idxv = *idxp;
    const int K = (idxv == 0) ? 512 : 1024;
    const int nch = K >> 8;
    const int pbase = blockIdx.x * CTA_PIX;

    // ---- stage A tile (xh|xl) swizzled + shn2 into smem ----
    {
        int r = tid;
        int p = pbase + r;
        int b = p >> 12;
        size_t xb = (size_t)b * (D * HW) + (p & (HW - 1));
        #pragma unroll
        for (int j = 0; j < 32; j++) {
            float v0 = X[xb + (size_t)(2 * j) * HW];
            float v1 = X[xb + (size_t)(2 * j + 1) * HW];
            __nv_bfloat16 h0 = __float2bfloat16_rn(v0), h1 = __float2bfloat16_rn(v1);
            __nv_bfloat16 l0 = __float2bfloat16_rn(v0 - __bfloat162float(h0));
            __nv_bfloat16 l1 = __float2bfloat16_rn(v1 - __bfloat162float(h1));
            uint32_t hp = (uint32_t)__bfloat16_as_ushort(h0)
                        | ((uint32_t)__bfloat16_as_ushort(h1) << 16);
            uint32_t lp = (uint32_t)__bfloat16_as_ushort(l0)
                        | ((uint32_t)__bfloat16_as_ushort(l1) << 16);
            int u = j >> 2;                 // byte col 4j -> 16B unit
            int inb = (4 * j) & 15;
            *(uint32_t*)(smem + SM_A + r * 256 + (((u)     ^ (r & 7)) << 4) + inb) = hp;
            *(uint32_t*)(smem + SM_A + r * 256 + (((u + 8) ^ (r & 7)) << 4) + inb) = lp;
        }
        uint32_t* sh2 = (uint32_t*)(smem + SM_SHN2);
        for (int i = tid; i < KMAX; i += TPB) sh2[i] = g_shn2[i];
    }
    __syncthreads();

    // ---- load persistent A fragments: xh/xl [mtile][ktile][4 regs] ----
    uint32_t xh[2][4][4], xl[2][4][4];
    #pragma unroll
    for (int mt = 0; mt < 2; mt++)
        #pragma unroll
        for (int kt = 0; kt < 4; kt++) {
            int row = warp * 32 + mt * 16 + ((grp & 1) << 3) + lr;
            int uh = kt * 2 + (grp >> 1);
            LDSM_X4(xh[mt][kt][0], xh[mt][kt][1], xh[mt][kt][2], xh[mt][kt][3],
                    sb + SM_A + row * 256 + (((uh) ^ lr) << 4));
            int ul = 8 + kt * 2 + (grp >> 1);
            LDSM_X4(xl[mt][kt][0], xl[mt][kt][1], xl[mt][kt][2], xl[mt][kt][3],
                    sb + SM_A + row * 256 + (((ul) ^ lr) << 4));
        }
    __syncthreads();   // A region dead: B chunks may now overwrite it

    // top-2 per pixel-slot: slot = mt*2 + rowhalf (rows lane/4 and lane/4+8)
    float s1[4], s2[4];
    int i1[4], i2[4];
    #pragma unroll
    for (int sl = 0; sl < 4; sl++) { s1[sl] = -3.4e38f; s2[sl] = -3.4e38f; i1[sl] = 0; i2[sl] = 0; }

    const uint32_t aext = (q == 0) ? 0x3F803F80u : 0u;   // (1.0,1.0) bf16
    const uint32_t* sh2 = (const uint32_t*)(smem + SM_SHN2);

    for (int ch = 0; ch < nch; ch++) {
        // stage B chunk (64 KB, swizzle preserved by raw copy) over dead A
        {
            const uint4* src = (const uint4*)(g_bsplit + (size_t)ch * 65536);
            uint4* dst = (uint4*)(smem + SM_B);
            #pragma unroll
            for (int i = 0; i < 16; i++) dst[tid + i * TPB] = src[tid + i * TPB];
        }
        __syncthreads();
        const int kb = ch << 8;

        #pragma unroll 1
        for (int ng = 0; ng < 16; ng++) {
            const int nt0 = ng * 2;
            float dx[2][2][4];                       // [mtile][ntile][reg]
            #pragma unroll
            for (int a = 0; a < 2; a++)
                #pragma unroll
                for (int bb = 0; bb < 2; bb++)
                    #pragma unroll
                    for (int c = 0; c < 4; c++) dx[a][bb][c] = 0.f;

            // norm k-tile: ones-column (k0,k1) x (-norm hi, -norm lo).
            // a0 = rows lane/4 @ k0-1, a1 = rows lane/4+8 @ k0-1 (both need ones)
            uint32_t be0 = 0, be1 = 0;
            if (q == 0) {
                be0 = sh2[kb + nt0 * 8 + (lane >> 2)];
                be1 = sh2[kb + nt0 * 8 + 8 + (lane >> 2)];
            }
            MMA(dx[0][0], aext, aext, 0u, 0u, be0, 0u);
            MMA(dx[0][1], aext, aext, 0u, 0u, be1, 0u);
            MMA(dx[1][0], aext, aext, 0u, 0u, be0, 0u);
            MMA(dx[1][1], aext, aext, 0u, 0u, be1, 0u);

            #pragma unroll
            for (int s = 0; s < 3; s++) {            // xh.ch, xh.cl, xl.ch
                const int bsplit = (s == 1) ? 8 : 0;
                #pragma unroll
                for (int p2 = 0; p2 < 2; p2++) {     // ktile pairs
                    uint32_t b0[4], b1[4];
                    {
                        int u = bsplit + p2 * 4 + grp;
                        int row0 = nt0 * 8 + lr;
                        LDSM_X4(b0[0], b0[1], b0[2], b0[3],
                                sb + SM_B + row0 * 256 + (((u) ^ lr) << 4));
                        int row1 = (nt0 + 1) * 8 + lr;
                        LDSM_X4(b1[0], b1[1], b1[2], b1[3],
                                sb + SM_B + row1 * 256 + (((u) ^ lr) << 4));
                    }
                    #pragma unroll
                    for (int k2 = 0; k2 < 2; k2++) {
                        const int kt = p2 * 2 + k2;
                        if (s == 2) {
                            MMA(dx[0][0], xl[0][kt][0], xl[0][kt][1], xl[0][kt][2], xl[0][kt][3], b0[k2*2], b0[k2*2+1]);
                            MMA(dx[0][1], xl[0][kt][0], xl[0][kt][1], xl[0][kt][2], xl[0][kt][3], b1[k2*2], b1[k2*2+1]);
                            MMA(dx[1][0], xl[1][kt][0], xl[1][kt][1], xl[1][kt][2], xl[1][kt][3], b0[k2*2], b0[k2*2+1]);
                            MMA(dx[1][1], xl[1][kt][0], xl[1][kt][1], xl[1][kt][2], xl[1][kt][3], b1[k2*2], b1[k2*2+1]);
                        } else {
                            MMA(dx[0][0], xh[0][kt][0], xh[0][kt][1], xh[0][kt][2], xh[0][kt][3], b0[k2*2], b0[k2*2+1]);
                            MMA(dx[0][1], xh[0][kt][0], xh[0][kt][1], xh[0][kt][2], xh[0][kt][3], b1[k2*2], b1[k2*2+1]);
                            MMA(dx[1][0], xh[1][kt][0], xh[1][kt][1], xh[1][kt][2], xh[1][kt][3], b0[k2*2], b0[k2*2+1]);
                            MMA(dx[1][1], xh[1][kt][0], xh[1][kt][1], xh[1][kt][2], xh[1][kt][3], b1[k2*2], b1[k2*2+1]);
                        }
                    }
                }
            }

            // epilogue: top-2 update. D frag: d0,d1 = (row lane/4, cols n,n+1);
            // d2,d3 = (row lane/4+8, cols n,n+1); n = kb + ntile*8 + 2q
            #pragma unroll
            for (int mt = 0; mt < 2; mt++)
                #pragma unroll
                for (int j = 0; j < 2; j++) {
                    const int nb = kb + (nt0 + j) * 8 + q * 2;
                    #pragma unroll
                    for (int e = 0; e < 4; e++) {
                        const int sl = mt * 2 + (e >> 1);
                        const int kk = nb + (e & 1);
                        float v = dx[mt][j][e];
                        if (v > s2[sl]) {
                            if (v > s1[sl]) { s2[sl] = s1[sl]; i2[sl] = i1[sl]; s1[sl] = v; i1[sl] = kk; }
                            else            { s2[sl] = v; i2[sl] = kk; }
                        }
                    }
                }
        }
        __syncthreads();
    }

    // ---- merge top-2 across the quad (lanes sharing a row) ----
    #pragma unroll
    for (int sl = 0; sl < 4; sl++) {
        #pragma unroll
        for (int m = 1; m <= 2; m <<= 1) {
            float o1 = __shfl_xor_sync(0xffffffffu, s1[sl], m);
            float o2 = __shfl_xor_sync(0xffffffffu, s2[sl], m);
            int oi1 = __shfl_xor_sync(0xffffffffu, i1[sl], m);
            int oi2 = __shfl_xor_sync(0xffffffffu, i2[sl], m);
            if (o1 > s1[sl]) {
                float ns2; int ni2;
                if (o2 > s1[sl]) { ns2 = o2; ni2 = oi2; }
                else             { ns2 = s1[sl]; ni2 = i1[sl]; }
                s1[sl] = o1; i1[sl] = oi1; s2[sl] = ns2; i2[sl] = ni2;
            } else if (o1 > s2[sl]) { s2[sl] = o1; i2[sl] = oi1; }
        }
    }
    if (q == 0) {
        #pragma unroll
        for (int sl = 0; sl < 4; sl++) {
            int mt = sl >> 1, rs = sl & 1;
            int pl = warp * 32 + mt * 16 + rs * 8 + (lane >> 2);
            ((float*)(smem + SM_S1))[pl] = s1[sl];
            ((float*)(smem + SM_S2))[pl] = s2[sl];
            ((int*)(smem + SM_I1))[pl] = i1[sl];
            ((int*)(smem + SM_I2))[pl] = i2[sl];
        }
    }
    __syncthreads();

    // ---- phase 2: rescue near-ties, then gather/output/loss/hist ----
    {
        int p = pbase + tid;
        int b = p >> 12;
        size_t xb = (size_t)b * (D * HW) + (p & (HW - 1));
        float fs1 = ((float*)(smem + SM_S1))[tid];
        float fs2 = ((float*)(smem + SM_S2))[tid];
        int w1 = ((int*)(smem + SM_I1))[tid];
        int w2 = ((int*)(smem + SM_I2))[tid];

        if (fs1 - fs2 < 4e-3f) {                 // covers split + norm error
            const float* c1 = code_row(w1, e0, e1, e2, idxv);
            const float* c2 = code_row(w2, e0, e1, e2, idxv);
            double d1 = 0.0, d2 = 0.0;
            for (int d = 0; d < D; d++) {
                double xv = (double)X[xb + (size_t)d * HW];
                double t1 = xv - (double)c1[d]; d1 += t1 * t1;
                double t2 = xv - (double)c2[d]; d2 += t2 * t2;
            }
            if (d2 < d1 || (d2 == d1 && w2 < w1)) w1 = w2;
        }
        atomicAdd(&g_hist[w1], 1);

        const float* cw = code_row(w1, e0, e1, e2, idxv);
        float lsum = 0.f;
        #pragma unroll 8
        for (int d = 0; d < D; d++) {
            float xv = X[xb + (size_t)d * HW];
            float df = cw[d] - xv;
            out[xb + (size_t)d * HW] = xv + df;   // STE, reference rounding
            lsum += df * df;
        }
        float* red = (float*)(smem + SM_RED);
        red[tid] = lsum;
        __syncthreads();
        for (int off = TPB / 2; off > 0; off >>= 1) {
            if (tid < off) red[tid] += red[tid + off];
            __syncthreads();
        }
        if (tid == 0) atomicAdd(&g_lossacc, red[0]);
    }
}

// ---------------------------------------------------------------------------
// Kernel 3: finalize loss + perplexity
// ---------------------------------------------------------------------------
__global__ void finalize_kernel(const int* __restrict__ idxp, float* __restrict__ out,
                                int out_size) {
    __shared__ float red[1024];
    int t = threadIdx.x;
    int idxv = *idxp;
    int K = (idxv == 0) ? 512 : 1024;
    float v = 0.f;
    if (t < K) {
        float pr = (float)g_hist[t] * (1.0f / (float)NPIX);
        v = pr * logf(pr + 1e-10f);
    }
    red[t] = v;
    __syncthreads();
    for (int off = 512; off > 0; off >>= 1) {
        if (t < off) red[t] += red[t + off];
        __syncthreads();
    }
    if (t == 0) {
        float mse = g_lossacc / (float)OUT_ELEMS;
        out[OUT_ELEMS]     = mse + 0.25f * mse;   // q_latent + 0.25*e_latent
        out[OUT_ELEMS + 1] = expf(-red[0]);       // perplexity
    }
    for (int i = OUT_ELEMS + 2 + t; i < out_size; i += 1024) out[i] = 0.f;
}

// ---------------------------------------------------------------------------
extern "C" void kernel_launch(void* const* d_in, const int* in_sizes, int n_in,
                              void* d_out, int out_size) {
    const float* x  = (const float*)d_in[0];
    const float* e0 = (const float*)d_in[1];
    const float* e1 = (const float*)d_in[2];
    const float* e2 = (const float*)d_in[3];
    const int*   ip = (const int*)d_in[4];
    float* out = (float*)d_out;

    cudaFuncSetAttribute(vq_hmma, cudaFuncAttributeMaxDynamicSharedMemorySize,
                         SMEM_TOTAL);

    prep_norms<<<256, 128>>>(e0, e1, e2, ip);
    prep_bsplit<<<KMAX, 64>>>(e0, e1, e2, ip);
    vq_hmma<<<NPIX / CTA_PIX, TPB, SMEM_TOTAL>>>(x, e0, e1, e2, ip, out);
    finalize_kernel<<<1, 1024>>>(ip, out, out_size);
}